// round 3
// baseline (speedup 1.0000x reference)
#include <cuda_runtime.h>

// Problem constants (fixed by the dataset)
#define NN 100000
#define EE 3200000
#define FF 128
#define HH 16

#define SCAN_BLK 1024
#define NBLK_SCAN ((NN + SCAN_BLK - 1) / SCAN_BLK)   // 98

// ---- static device scratch (no allocations allowed) ----
__device__ int   g_cnt[NN];        // in-degree (excl. self loop)
__device__ int   g_off[NN + 1];    // CSR offsets (by dst)
__device__ int   g_cur[NN];        // fill cursors
__device__ int   g_bsum[NBLK_SCAN];
__device__ int   g_csr[EE];        // src indices grouped by dst
__device__ float g_dis[NN];        // deg^{-1/2}
__device__ float g_u[NN * HH];     // (x @ W1) * dis  per node
__device__ float g_v[NN];          // (relu(conv1) @ W2) * dis per node

// K0: zero degree counters
__global__ void k_zero() {
    int i = blockIdx.x * blockDim.x + threadIdx.x;
    if (i < NN) g_cnt[i] = 0;
}

// K1: count in-degree over dst
__global__ void k_count(const int* __restrict__ dst) {
    int e = blockIdx.x * blockDim.x + threadIdx.x;
    if (e < EE) atomicAdd(&g_cnt[dst[e]], 1);
}

// K2: per-block exclusive scan of counts
__global__ void k_scan1() {
    __shared__ int sh[SCAN_BLK];
    int tid = threadIdx.x;
    int i = blockIdx.x * SCAN_BLK + tid;
    int v = (i < NN) ? g_cnt[i] : 0;
    sh[tid] = v;
    __syncthreads();
    for (int d = 1; d < SCAN_BLK; d <<= 1) {
        int t = (tid >= d) ? sh[tid - d] : 0;
        __syncthreads();
        sh[tid] += t;
        __syncthreads();
    }
    if (i < NN) g_off[i] = sh[tid] - v;          // exclusive prefix within block
    if (tid == SCAN_BLK - 1) g_bsum[blockIdx.x] = sh[tid];
}

// K3: scan the 98 block sums (tiny, serial)
__global__ void k_scan2() {
    if (threadIdx.x == 0 && blockIdx.x == 0) {
        int acc = 0;
        for (int b = 0; b < NBLK_SCAN; b++) {
            int t = g_bsum[b];
            g_bsum[b] = acc;
            acc += t;
        }
    }
}

// K4: finalize offsets, init cursors, compute dis = rsqrt(deg+1)
__global__ void k_finish_off() {
    int i = blockIdx.x * blockDim.x + threadIdx.x;
    if (i < NN) {
        int off = g_off[i] + g_bsum[i / SCAN_BLK];
        g_off[i] = off;
        g_cur[i] = off;
        g_dis[i] = rsqrtf((float)(g_cnt[i] + 1));
    }
    if (i == 0) g_off[NN] = EE;
}

// K5: fill CSR (src grouped by dst)
__global__ void k_fill(const int* __restrict__ src, const int* __restrict__ dst) {
    int e = blockIdx.x * blockDim.x + threadIdx.x;
    if (e < EE) {
        int p = atomicAdd(&g_cur[dst[e]], 1);
        g_csr[p] = src[e];
    }
}

// K6: u[i,:] = (x[i,:] @ W1) * dis[i]   (8 nodes per 128-thread block)
__global__ void k_gemm1(const float* __restrict__ x, const float* __restrict__ W1) {
    __shared__ float Wsh[FF * HH];   // 8 KB
    __shared__ float xsh[8][FF];     // 4 KB
    int tid = threadIdx.x;
    for (int k = tid; k < FF * HH; k += 128) Wsh[k] = W1[k];
    int node0 = blockIdx.x * 8;
    const float4* xv = (const float4*)(x + (size_t)node0 * FF);
    // 8 rows * 128 floats = 256 float4; 128 threads -> 2 iters, coalesced
    float4* xsv = (float4*)&xsh[0][0];
    for (int idx = tid; idx < 8 * FF / 4; idx += 128) xsv[idx] = xv[idx];
    __syncthreads();

    int r = tid / HH, h = tid % HH;
    int node = node0 + r;
    float acc = 0.f;
#pragma unroll 16
    for (int k = 0; k < FF; k++) acc += xsh[r][k] * Wsh[k * HH + h];
    g_u[node * HH + h] = acc * g_dis[node];
}

// K7: layer-1 aggregate + relu + layer-2 projection.
// 16 lanes per node; lane h owns hidden channel h.
__global__ void k_agg1(const float* __restrict__ b1, const float* __restrict__ W2) {
    int t = blockIdx.x * blockDim.x + threadIdx.x;   // blockDim = 256, exact fit
    int node = t / HH;
    int h = t % HH;
    int beg = g_off[node], end = g_off[node + 1];
    float acc = 0.f;
    for (int e = beg; e < end; e++) {
        int s = g_csr[e];                 // broadcast within the 16-lane group
        acc += g_u[s * HH + h];           // 16 lanes -> 64B contiguous gather
    }
    acc += g_u[node * HH + h];            // self loop
    float dis = g_dis[node];
    float h2 = fmaxf(fmaf(dis, acc, b1[h]), 0.f);
    float p = h2 * W2[h];
#pragma unroll
    for (int d = 8; d >= 1; d >>= 1)
        p += __shfl_down_sync(0xFFFFFFFFu, p, d, 16);   // segmented 16-wide reduce
    if (h == 0) g_v[node] = dis * p;
}

// K8: layer-2 aggregate -> output. One warp per node.
__global__ void k_agg2(const float* __restrict__ b2, float* __restrict__ out) {
    int warp = (blockIdx.x * blockDim.x + threadIdx.x) >> 5;
    int lane = threadIdx.x & 31;
    if (warp >= NN) return;
    int beg = g_off[warp], end = g_off[warp + 1];
    float acc = 0.f;
    for (int e = beg + lane; e < end; e += 32) acc += g_v[g_csr[e]];
#pragma unroll
    for (int d = 16; d >= 1; d >>= 1)
        acc += __shfl_down_sync(0xFFFFFFFFu, acc, d);
    if (lane == 0) out[warp] = g_dis[warp] * (acc + g_v[warp]) + b2[0];
}

extern "C" void kernel_launch(void* const* d_in, const int* in_sizes, int n_in,
                              void* d_out, int out_size) {
    const float* x  = (const float*)d_in[0];
    const int*   ei = (const int*)d_in[1];
    const float* W1 = (const float*)d_in[2];
    const float* b1 = (const float*)d_in[3];
    const float* W2 = (const float*)d_in[4];
    const float* b2 = (const float*)d_in[5];
    float* out = (float*)d_out;

    const int* src = ei;         // edge_index[0]
    const int* dst = ei + EE;    // edge_index[1]

    k_zero<<<(NN + 255) / 256, 256>>>();
    k_count<<<(EE + 255) / 256, 256>>>(dst);
    k_scan1<<<NBLK_SCAN, SCAN_BLK>>>();
    k_scan2<<<1, 32>>>();
    k_finish_off<<<(NN + 255) / 256, 256>>>();
    k_fill<<<(EE + 255) / 256, 256>>>(src, dst);
    k_gemm1<<<NN / 8, 128>>>(x, W1);
    k_agg1<<<(NN * HH) / 256, 256>>>(b1, W2);
    k_agg2<<<(NN * 32 + 255) / 256, 256>>>(b2, out);
}